// round 2
// baseline (speedup 1.0000x reference)
#include <cuda_runtime.h>

// Problem constants
#define BATCH 16
#define CCH   512
#define NPIX  4096          // 64*64
#define NHEAD 8
#define HDIM  64
#define EPS   1e-6f

// GEMM tile config
#define BM 128
#define BN 128
#define BK 16

// Scratch (device globals - no allocation at launch time).
// g_V is reused: first holds V = w_v @ x, then (after kv_kernel consumes it)
// the normalized attention output written by attn_out_kernel.
__device__ float g_QK[(size_t)BATCH * 1024 * NPIX];   // relu(w_qk @ (x+pos)): q = ch 0..511, k = ch 512..1023
__device__ float g_V [(size_t)BATCH * CCH  * NPIX];   // V, then attention output (reused)
__device__ float g_KV[(size_t)BATCH * NHEAD * 65 * 64];

// ---------------------------------------------------------------------------
// Batched GEMM: C[b] (MxN) = A (MxK, shared) * X[b] (KxN), optional X0+X1 fuse
// and optional relu epilogue. Row-major everywhere, N contiguous.
// 256 threads, 128x128 tile, 8x8 per thread, BK=16.
// ---------------------------------------------------------------------------
template<bool FUSE_ADD, bool RELU>
__global__ __launch_bounds__(256) void gemm_kernel(
    const float* __restrict__ A,
    const float* __restrict__ X0,
    const float* __restrict__ X1,
    float* __restrict__ C,
    int M, int K, int N)
{
    const int b = blockIdx.z;
    const float* X0b = X0 + (size_t)b * K * N;
    const float* X1b = FUSE_ADD ? (X1 + (size_t)b * K * N) : nullptr;
    float* Cb = C + (size_t)b * M * N;

    const int tileM = blockIdx.y * BM;
    const int tileN = blockIdx.x * BN;

    __shared__ float As[BM][BK];   // [m][k]
    __shared__ float Xs[BK][BN];   // [k][n]

    const int tid = threadIdx.x;
    const int tx = tid & 15;       // col group
    const int ty = tid >> 4;       // row group

    float acc[8][8];
#pragma unroll
    for (int i = 0; i < 8; i++)
#pragma unroll
        for (int j = 0; j < 8; j++) acc[i][j] = 0.0f;

    for (int k0 = 0; k0 < K; k0 += BK) {
        // Load A tile: 128x16 = 512 float4, 2 per thread
#pragma unroll
        for (int i = 0; i < 2; i++) {
            int e4 = tid + i * 256;           // 0..511
            int r  = e4 >> 2;                 // 0..127
            int kq = e4 & 3;                  // 0..3
            float4 a = *(const float4*)(A + (size_t)(tileM + r) * K + k0 + kq * 4);
            *(float4*)(&As[r][kq * 4]) = a;
        }
        // Load X tile: 16x128 = 512 float4
#pragma unroll
        for (int i = 0; i < 2; i++) {
            int e4 = tid + i * 256;
            int kk = e4 >> 5;                 // 0..15
            int n4 = e4 & 31;                 // 0..31
            size_t off = (size_t)(k0 + kk) * N + tileN + n4 * 4;
            float4 xv = *(const float4*)(X0b + off);
            if (FUSE_ADD) {
                float4 pv = *(const float4*)(X1b + off);
                xv.x += pv.x; xv.y += pv.y; xv.z += pv.z; xv.w += pv.w;
            }
            *(float4*)(&Xs[kk][n4 * 4]) = xv;
        }
        __syncthreads();

#pragma unroll
        for (int k = 0; k < BK; k++) {
            float a[8], xr[8];
#pragma unroll
            for (int i = 0; i < 8; i++) a[i] = As[ty * 8 + i][k];
            float4 x0 = *(float4*)(&Xs[k][tx * 8]);
            float4 x1 = *(float4*)(&Xs[k][tx * 8 + 4]);
            xr[0] = x0.x; xr[1] = x0.y; xr[2] = x0.z; xr[3] = x0.w;
            xr[4] = x1.x; xr[5] = x1.y; xr[6] = x1.z; xr[7] = x1.w;
#pragma unroll
            for (int i = 0; i < 8; i++)
#pragma unroll
                for (int j = 0; j < 8; j++)
                    acc[i][j] += a[i] * xr[j];
        }
        __syncthreads();
    }

    // Store
#pragma unroll
    for (int i = 0; i < 8; i++) {
        int m = tileM + ty * 8 + i;
#pragma unroll
        for (int j = 0; j < 8; j += 4) {
            float4 v;
            v.x = acc[i][j + 0]; v.y = acc[i][j + 1];
            v.z = acc[i][j + 2]; v.w = acc[i][j + 3];
            if (RELU) {
                v.x = fmaxf(v.x, 0.0f); v.y = fmaxf(v.y, 0.0f);
                v.z = fmaxf(v.z, 0.0f); v.w = fmaxf(v.w, 0.0f);
            }
            *(float4*)(Cb + (size_t)m * N + tileN + tx * 8 + j) = v;
        }
    }
}

// Wrappers binding the device-global scratch (no host symbol lookups needed).
__global__ __launch_bounds__(256) void gemm_qk_kernel(
    const float* __restrict__ A, const float* __restrict__ X0,
    const float* __restrict__ X1, int M, int K, int N)
{
    // forward body via inline call is not possible for __global__; duplicate
    // dispatch instead: see kernel_launch (we pass g_QK pointer via constant
    // trick). This wrapper is unused.
}

// ---------------------------------------------------------------------------
// KV kernel: per (b,h): kv[e][d] = sum_n v[e][n]*k[d][n] for e,d in [0,64),
// plus kv[64][d] = sum_n k[d][n] (the ones-row of v_pad).
// One block per (b,h) = 128 blocks, 256 threads, 4x4 per thread (16x16 grid).
// ---------------------------------------------------------------------------
__global__ __launch_bounds__(256) void kv_kernel()
{
    const int bh = blockIdx.x;
    const int b = bh >> 3, h = bh & 7;
    const float* kp = g_QK + ((size_t)b * 1024 + 512 + h * 64) * NPIX;
    const float* vp = g_V  + ((size_t)b * 512  +       h * 64) * NPIX;

    __shared__ float Vs[64][65];   // [nn][e]
    __shared__ float Ks[64][65];   // [nn][d]

    const int tid = threadIdx.x;
    const int tx = tid & 15;       // d group
    const int ty = tid >> 4;       // e group

    float acc[4][4];
#pragma unroll
    for (int i = 0; i < 4; i++)
#pragma unroll
        for (int j = 0; j < 4; j++) acc[i][j] = 0.0f;
    float ksum = 0.0f;

    for (int n0 = 0; n0 < NPIX; n0 += 64) {
        // Load 64x64 tiles (transposed into smem), 16 elems each per thread
#pragma unroll
        for (int i = 0; i < 16; i++) {
            int idx = tid + i * 256;          // 0..4095
            int e  = idx >> 6;
            int nn = idx & 63;
            Vs[nn][e] = vp[(size_t)e * NPIX + n0 + nn];
            Ks[nn][e] = kp[(size_t)e * NPIX + n0 + nn];
        }
        __syncthreads();

#pragma unroll 8
        for (int nn = 0; nn < 64; nn++) {
            float vv[4], kk[4];
#pragma unroll
            for (int i = 0; i < 4; i++) vv[i] = Vs[nn][ty * 4 + i];
#pragma unroll
            for (int j = 0; j < 4; j++) kk[j] = Ks[nn][tx * 4 + j];
#pragma unroll
            for (int i = 0; i < 4; i++)
#pragma unroll
                for (int j = 0; j < 4; j++)
                    acc[i][j] += vv[i] * kk[j];
        }
        if (tid < 64) {
#pragma unroll 8
            for (int nn = 0; nn < 64; nn++) ksum += Ks[nn][tid];
        }
        __syncthreads();
    }

    float* kvb = g_KV + (size_t)bh * 65 * 64;
#pragma unroll
    for (int i = 0; i < 4; i++)
#pragma unroll
        for (int j = 0; j < 4; j++)
            kvb[(ty * 4 + i) * 64 + tx * 4 + j] = acc[i][j];
    if (tid < 64) kvb[64 * 64 + tid] = ksum;
}

// ---------------------------------------------------------------------------
// Attention output: per (b,h), per pixel n:
//   norm = sum_d kv[64][d]*q[d][n];  out[e][n] = (sum_d kv[e][d]*q[d][n]) / (norm+eps)
// grid (NPIX/256, B*NH), 256 threads, one pixel per thread.
// Writes the result in-place into g_V (V data already consumed by kv_kernel).
// ---------------------------------------------------------------------------
__global__ __launch_bounds__(256) void attn_out_kernel()
{
    const int bh = blockIdx.y;
    const int b = bh >> 3, h = bh & 7;
    const int n = blockIdx.x * 256 + threadIdx.x;

    __shared__ float kvs[65][64];
    const float* kvb = g_KV + (size_t)bh * 65 * 64;
    for (int i = threadIdx.x; i < 65 * 64; i += 256)
        ((float*)kvs)[i] = kvb[i];
    __syncthreads();

    const float* q = g_QK + ((size_t)b * 1024 + h * 64) * NPIX;
    float qr[64];
#pragma unroll
    for (int d = 0; d < 64; d++) qr[d] = q[(size_t)d * NPIX + n];

    // normalizer row
    float norm = 0.0f;
#pragma unroll
    for (int d = 0; d < 64; d += 4) {
        float4 kk = *(float4*)(&kvs[64][d]);
        norm += kk.x * qr[d] + kk.y * qr[d + 1] + kk.z * qr[d + 2] + kk.w * qr[d + 3];
    }
    const float inv = 1.0f / (norm + EPS);

    float* ob = g_V + ((size_t)b * 512 + h * 64) * NPIX + n;
#pragma unroll 2
    for (int e = 0; e < 64; e++) {
        float s = 0.0f;
#pragma unroll
        for (int d = 0; d < 64; d += 4) {
            float4 kk = *(float4*)(&kvs[e][d]);
            s += kk.x * qr[d] + kk.y * qr[d + 1] + kk.z * qr[d + 2] + kk.w * qr[d + 3];
        }
        ob[(size_t)e * NPIX] = s * inv;
    }
}

// ---------------------------------------------------------------------------
// GEMM entry kernels that bind device-global scratch directly (avoids any
// host-side cudaGetSymbolAddress during graph capture).
// ---------------------------------------------------------------------------
__global__ __launch_bounds__(256) void gemm_qk(
    const float* __restrict__ A, const float* __restrict__ x,
    const float* __restrict__ pos);
__global__ __launch_bounds__(256) void gemm_v(
    const float* __restrict__ A, const float* __restrict__ x);
__global__ __launch_bounds__(256) void gemm_o(
    const float* __restrict__ A, float* __restrict__ out);

// Shared GEMM body as a __device__ function.
template<bool FUSE_ADD, bool RELU>
__device__ __forceinline__ void gemm_body(
    const float* __restrict__ A,
    const float* __restrict__ X0,
    const float* __restrict__ X1,
    float* __restrict__ C,
    int M, int K, int N)
{
    const int b = blockIdx.z;
    const float* X0b = X0 + (size_t)b * K * N;
    const float* X1b = FUSE_ADD ? (X1 + (size_t)b * K * N) : nullptr;
    float* Cb = C + (size_t)b * M * N;

    const int tileM = blockIdx.y * BM;
    const int tileN = blockIdx.x * BN;

    __shared__ float As[BM][BK];
    __shared__ float Xs[BK][BN];

    const int tid = threadIdx.x;
    const int tx = tid & 15;
    const int ty = tid >> 4;

    float acc[8][8];
#pragma unroll
    for (int i = 0; i < 8; i++)
#pragma unroll
        for (int j = 0; j < 8; j++) acc[i][j] = 0.0f;

    for (int k0 = 0; k0 < K; k0 += BK) {
#pragma unroll
        for (int i = 0; i < 2; i++) {
            int e4 = tid + i * 256;
            int r  = e4 >> 2;
            int kq = e4 & 3;
            float4 a = *(const float4*)(A + (size_t)(tileM + r) * K + k0 + kq * 4);
            *(float4*)(&As[r][kq * 4]) = a;
        }
#pragma unroll
        for (int i = 0; i < 2; i++) {
            int e4 = tid + i * 256;
            int kk = e4 >> 5;
            int n4 = e4 & 31;
            size_t off = (size_t)(k0 + kk) * N + tileN + n4 * 4;
            float4 xv = *(const float4*)(X0b + off);
            if (FUSE_ADD) {
                float4 pv = *(const float4*)(X1b + off);
                xv.x += pv.x; xv.y += pv.y; xv.z += pv.z; xv.w += pv.w;
            }
            *(float4*)(&Xs[kk][n4 * 4]) = xv;
        }
        __syncthreads();

#pragma unroll
        for (int k = 0; k < BK; k++) {
            float a[8], xr[8];
#pragma unroll
            for (int i = 0; i < 8; i++) a[i] = As[ty * 8 + i][k];
            float4 x0 = *(float4*)(&Xs[k][tx * 8]);
            float4 x1 = *(float4*)(&Xs[k][tx * 8 + 4]);
            xr[0] = x0.x; xr[1] = x0.y; xr[2] = x0.z; xr[3] = x0.w;
            xr[4] = x1.x; xr[5] = x1.y; xr[6] = x1.z; xr[7] = x1.w;
#pragma unroll
            for (int i = 0; i < 8; i++)
#pragma unroll
                for (int j = 0; j < 8; j++)
                    acc[i][j] += a[i] * xr[j];
        }
        __syncthreads();
    }

#pragma unroll
    for (int i = 0; i < 8; i++) {
        int m = tileM + ty * 8 + i;
#pragma unroll
        for (int j = 0; j < 8; j += 4) {
            float4 v;
            v.x = acc[i][j + 0]; v.y = acc[i][j + 1];
            v.z = acc[i][j + 2]; v.w = acc[i][j + 3];
            if (RELU) {
                v.x = fmaxf(v.x, 0.0f); v.y = fmaxf(v.y, 0.0f);
                v.z = fmaxf(v.z, 0.0f); v.w = fmaxf(v.w, 0.0f);
            }
            *(float4*)(Cb + (size_t)m * N + tileN + tx * 8 + j) = v;
        }
    }
}

__global__ __launch_bounds__(256) void gemm_qk(
    const float* __restrict__ A, const float* __restrict__ x,
    const float* __restrict__ pos)
{
    gemm_body<true, true>(A, x, pos, g_QK, 1024, CCH, NPIX);
}

__global__ __launch_bounds__(256) void gemm_v(
    const float* __restrict__ A, const float* __restrict__ x)
{
    gemm_body<false, false>(A, x, nullptr, g_V, 512, CCH, NPIX);
}

__global__ __launch_bounds__(256) void gemm_o(
    const float* __restrict__ A, float* __restrict__ out)
{
    gemm_body<false, false>(A, g_V, nullptr, out, 512, CCH, NPIX);
}

// ---------------------------------------------------------------------------
extern "C" void kernel_launch(void* const* d_in, const int* in_sizes, int n_in,
                              void* d_out, int out_size)
{
    const float* x    = (const float*)d_in[0];
    const float* pos  = (const float*)d_in[1];
    const float* w_qk = (const float*)d_in[2];
    const float* w_v  = (const float*)d_in[3];
    const float* w_o  = (const float*)d_in[4];
    float* out = (float*)d_out;

    dim3 thr(256);

    // 1) qk = relu(w_qk @ (x+pos))   [B,1024,N]
    gemm_qk<<<dim3(NPIX / BN, 1024 / BM, BATCH), thr>>>(w_qk, x, pos);

    // 2) v = w_v @ x                 [B,512,N]
    gemm_v<<<dim3(NPIX / BN, 512 / BM, BATCH), thr>>>(w_v, x);

    // 3) kv = v_pad @ k^T            [B,H,65,64]
    kv_kernel<<<BATCH * NHEAD, 256>>>();

    // 4) out = normalize(kv @ q)     [B,512,N]  (in-place over g_V)
    attn_out_kernel<<<dim3(NPIX / 256, BATCH * NHEAD), 256>>>();

    // 5) final = w_o @ out           [B,512,N]
    gemm_o<<<dim3(NPIX / BN, 512 / BM, BATCH), thr>>>(w_o, out);
}

// round 3
// speedup vs baseline: 2.0264x; 2.0264x over previous
#include <cuda_runtime.h>
#include <cstdint>

// Problem constants
#define BATCH 16
#define CCH   512
#define NPIX  4096          // 64*64
#define NHEAD 8
#define HDIM  64
#define EPS   1e-6f

// Tensor-core GEMM tile config
#define BMT 128
#define BNT 128
#define BKT 32

// Scratch (device globals - no allocation at launch time).
// g_V holds V = w_v @ x, then (after kv_kernel consumes it) the normalized
// attention output written by attn_out_kernel.
__device__ float g_QK[(size_t)BATCH * 1024 * NPIX];   // relu(w_qk @ (x+pos)): q = ch 0..511, k = ch 512..1023
__device__ float g_V [(size_t)BATCH * CCH  * NPIX];   // V, then attention output (reused)
__device__ float g_KV[(size_t)BATCH * NHEAD * 65 * 64];

// ---------------------------------------------------------------------------
// tf32 helpers
// ---------------------------------------------------------------------------
__device__ __forceinline__ uint32_t f2tf32(float f) {
    uint32_t r;
    asm("cvt.rna.tf32.f32 %0, %1;" : "=r"(r) : "f"(f));
    return r;
}

__device__ __forceinline__ void mma_tf32(
    float& c0, float& c1, float& c2, float& c3,
    uint32_t a0, uint32_t a1, uint32_t a2, uint32_t a3,
    uint32_t b0, uint32_t b1)
{
    asm volatile(
        "mma.sync.aligned.m16n8k8.row.col.f32.tf32.tf32.f32 "
        "{%0,%1,%2,%3}, {%4,%5,%6,%7}, {%8,%9}, {%0,%1,%2,%3};"
        : "+f"(c0), "+f"(c1), "+f"(c2), "+f"(c3)
        : "r"(a0), "r"(a1), "r"(a2), "r"(a3), "r"(b0), "r"(b1));
}

// ---------------------------------------------------------------------------
// Tensor-core batched GEMM: C[b] (MxN) = A (MxK shared weights) * X[b] (KxN)
// Row-major. 256 threads, 128x128 tile, BK=32.
// 8 warps in 4x2 grid; each warp computes 32x64 via m16n8k8 tf32 mma.
// Register-staged global loads overlap ldg with compute on previous tile.
// ---------------------------------------------------------------------------
#define AS_STRIDE 36    // pad: (group*36+tig)%32 = (group*4+tig)%32 -> conflict-free
#define XS_STRIDE 136   // pad: (tig*136+group)%32 = (tig*8+group)%32 -> conflict-free

template<bool FUSE_ADD, bool RELU>
__device__ __forceinline__ void gemm_tc_body(
    const float* __restrict__ A,
    const float* __restrict__ X0,
    const float* __restrict__ X1,
    float* __restrict__ C,
    int M, int K, int N)
{
    const int b = blockIdx.z;
    const float* X0b = X0 + (size_t)b * K * N;
    const float* X1b = FUSE_ADD ? (X1 + (size_t)b * K * N) : nullptr;
    float* Cb = C + (size_t)b * M * N;

    const int tileM = blockIdx.y * BMT;
    const int tileN = blockIdx.x * BNT;

    __shared__ float As[BMT][AS_STRIDE];   // [m][k]
    __shared__ float Xs[BKT][XS_STRIDE];   // [k][n]

    const int tid   = threadIdx.x;
    const int warp  = tid >> 5;
    const int lane  = tid & 31;
    const int group = lane >> 2;           // 0..7
    const int tig   = lane & 3;            // 0..3
    const int warp_m = warp >> 1;          // 0..3
    const int warp_n = warp & 1;           // 0..1
    const int m0 = warp_m * 32;
    const int n0 = warp_n * 64;

    float acc[2][8][4];
#pragma unroll
    for (int mt = 0; mt < 2; mt++)
#pragma unroll
        for (int nt = 0; nt < 8; nt++)
#pragma unroll
            for (int i = 0; i < 4; i++) acc[mt][nt][i] = 0.0f;

    // staging registers for the next tile
    float4 ar[4], xv[4];

    // ---- load tile k0 into registers ----
    auto load_regs = [&](int k0) {
#pragma unroll
        for (int i = 0; i < 4; i++) {
            int f = tid + i * 256;         // 0..1023 (float4 index)
            int arow = f >> 3, ac4 = f & 7;
            ar[i] = *(const float4*)(A + (size_t)(tileM + arow) * K + k0 + ac4 * 4);
            int krow = f >> 5, n4 = f & 31;
            size_t off = (size_t)(k0 + krow) * N + tileN + n4 * 4;
            float4 v = *(const float4*)(X0b + off);
            if (FUSE_ADD) {
                float4 p = *(const float4*)(X1b + off);
                v.x += p.x; v.y += p.y; v.z += p.z; v.w += p.w;
            }
            xv[i] = v;
        }
    };

    // ---- store staged registers into smem ----
    auto store_smem = [&]() {
#pragma unroll
        for (int i = 0; i < 4; i++) {
            int f = tid + i * 256;
            int arow = f >> 3, ac4 = f & 7;
            *(float4*)(&As[arow][ac4 * 4]) = ar[i];
            int krow = f >> 5, n4 = f & 31;
            *(float4*)(&Xs[krow][n4 * 4]) = xv[i];
        }
    };

    // ---- compute on current smem tile ----
    auto compute = [&]() {
#pragma unroll
        for (int ks = 0; ks < BKT / 8; ks++) {
            const int k = ks * 8;
            uint32_t af[2][4];
#pragma unroll
            for (int mt = 0; mt < 2; mt++) {
                int r = m0 + mt * 16 + group;
                af[mt][0] = f2tf32(As[r    ][k + tig]);
                af[mt][1] = f2tf32(As[r + 8][k + tig]);
                af[mt][2] = f2tf32(As[r    ][k + tig + 4]);
                af[mt][3] = f2tf32(As[r + 8][k + tig + 4]);
            }
            uint32_t bf[8][2];
#pragma unroll
            for (int nt = 0; nt < 8; nt++) {
                int c = n0 + nt * 8 + group;
                bf[nt][0] = f2tf32(Xs[k + tig    ][c]);
                bf[nt][1] = f2tf32(Xs[k + tig + 4][c]);
            }
#pragma unroll
            for (int mt = 0; mt < 2; mt++)
#pragma unroll
                for (int nt = 0; nt < 8; nt++)
                    mma_tf32(acc[mt][nt][0], acc[mt][nt][1],
                             acc[mt][nt][2], acc[mt][nt][3],
                             af[mt][0], af[mt][1], af[mt][2], af[mt][3],
                             bf[nt][0], bf[nt][1]);
        }
    };

    load_regs(0);
    store_smem();
    __syncthreads();

#pragma unroll 1
    for (int k0 = BKT; k0 < K; k0 += BKT) {
        load_regs(k0);       // ldg overlaps with compute below
        compute();
        __syncthreads();
        store_smem();
        __syncthreads();
    }
    compute();

    // ---- epilogue ----
#pragma unroll
    for (int mt = 0; mt < 2; mt++) {
        int r = tileM + m0 + mt * 16 + group;
#pragma unroll
        for (int nt = 0; nt < 8; nt++) {
            int c = tileN + n0 + nt * 8 + tig * 2;
            float2 v0, v1;
            v0.x = acc[mt][nt][0]; v0.y = acc[mt][nt][1];
            v1.x = acc[mt][nt][2]; v1.y = acc[mt][nt][3];
            if (RELU) {
                v0.x = fmaxf(v0.x, 0.0f); v0.y = fmaxf(v0.y, 0.0f);
                v1.x = fmaxf(v1.x, 0.0f); v1.y = fmaxf(v1.y, 0.0f);
            }
            *(float2*)(Cb + (size_t)r * N + c)       = v0;
            *(float2*)(Cb + (size_t)(r + 8) * N + c) = v1;
        }
    }
}

__global__ __launch_bounds__(256) void gemm_qk(
    const float* __restrict__ A, const float* __restrict__ x,
    const float* __restrict__ pos)
{
    gemm_tc_body<true, true>(A, x, pos, g_QK, 1024, CCH, NPIX);
}

__global__ __launch_bounds__(256) void gemm_v(
    const float* __restrict__ A, const float* __restrict__ x)
{
    gemm_tc_body<false, false>(A, x, nullptr, g_V, 512, CCH, NPIX);
}

__global__ __launch_bounds__(256) void gemm_o(
    const float* __restrict__ A, float* __restrict__ out)
{
    gemm_tc_body<false, false>(A, g_V, nullptr, out, 512, CCH, NPIX);
}

// ---------------------------------------------------------------------------
// KV kernel: per (b,h): kv[e][d] = sum_n v[e][n]*k[d][n] for e,d in [0,64),
// plus kv[64][d] = sum_n k[d][n] (the ones-row of v_pad).
// One block per (b,h) = 128 blocks, 256 threads, 4x4 per thread (16x16 grid).
// ---------------------------------------------------------------------------
__global__ __launch_bounds__(256) void kv_kernel()
{
    const int bh = blockIdx.x;
    const int b = bh >> 3, h = bh & 7;
    const float* kp = g_QK + ((size_t)b * 1024 + 512 + h * 64) * NPIX;
    const float* vp = g_V  + ((size_t)b * 512  +       h * 64) * NPIX;

    __shared__ float Vs[64][65];   // [nn][e]
    __shared__ float Ks[64][65];   // [nn][d]

    const int tid = threadIdx.x;
    const int tx = tid & 15;       // d group
    const int ty = tid >> 4;       // e group

    float acc[4][4];
#pragma unroll
    for (int i = 0; i < 4; i++)
#pragma unroll
        for (int j = 0; j < 4; j++) acc[i][j] = 0.0f;
    float ksum = 0.0f;

    for (int n0 = 0; n0 < NPIX; n0 += 64) {
#pragma unroll
        for (int i = 0; i < 16; i++) {
            int idx = tid + i * 256;          // 0..4095
            int e  = idx >> 6;
            int nn = idx & 63;
            Vs[nn][e] = vp[(size_t)e * NPIX + n0 + nn];
            Ks[nn][e] = kp[(size_t)e * NPIX + n0 + nn];
        }
        __syncthreads();

#pragma unroll 8
        for (int nn = 0; nn < 64; nn++) {
            float vv[4], kk[4];
#pragma unroll
            for (int i = 0; i < 4; i++) vv[i] = Vs[nn][ty * 4 + i];
#pragma unroll
            for (int j = 0; j < 4; j++) kk[j] = Ks[nn][tx * 4 + j];
#pragma unroll
            for (int i = 0; i < 4; i++)
#pragma unroll
                for (int j = 0; j < 4; j++)
                    acc[i][j] += vv[i] * kk[j];
        }
        if (tid < 64) {
#pragma unroll 8
            for (int nn = 0; nn < 64; nn++) ksum += Ks[nn][tid];
        }
        __syncthreads();
    }

    float* kvb = g_KV + (size_t)bh * 65 * 64;
#pragma unroll
    for (int i = 0; i < 4; i++)
#pragma unroll
        for (int j = 0; j < 4; j++)
            kvb[(ty * 4 + i) * 64 + tx * 4 + j] = acc[i][j];
    if (tid < 64) kvb[64 * 64 + tid] = ksum;
}

// ---------------------------------------------------------------------------
// Attention output: per (b,h), per pixel n:
//   norm = sum_d kv[64][d]*q[d][n];  out[e][n] = (sum_d kv[e][d]*q[d][n]) / (norm+eps)
// grid (NPIX/256, B*NH), 256 threads, one pixel per thread.
// Writes the result in-place into g_V (V data already consumed by kv_kernel).
// ---------------------------------------------------------------------------
__global__ __launch_bounds__(256) void attn_out_kernel()
{
    const int bh = blockIdx.y;
    const int b = bh >> 3, h = bh & 7;
    const int n = blockIdx.x * 256 + threadIdx.x;

    __shared__ float kvs[65][64];
    const float* kvb = g_KV + (size_t)bh * 65 * 64;
    for (int i = threadIdx.x; i < 65 * 64; i += 256)
        ((float*)kvs)[i] = kvb[i];
    __syncthreads();

    const float* q = g_QK + ((size_t)b * 1024 + h * 64) * NPIX;
    float qr[64];
#pragma unroll
    for (int d = 0; d < 64; d++) qr[d] = q[(size_t)d * NPIX + n];

    float norm = 0.0f;
#pragma unroll
    for (int d = 0; d < 64; d += 4) {
        float4 kk = *(float4*)(&kvs[64][d]);
        norm += kk.x * qr[d] + kk.y * qr[d + 1] + kk.z * qr[d + 2] + kk.w * qr[d + 3];
    }
    const float inv = 1.0f / (norm + EPS);

    float* ob = g_V + ((size_t)b * 512 + h * 64) * NPIX + n;
#pragma unroll 2
    for (int e = 0; e < 64; e++) {
        float s = 0.0f;
#pragma unroll
        for (int d = 0; d < 64; d += 4) {
            float4 kk = *(float4*)(&kvs[e][d]);
            s += kk.x * qr[d] + kk.y * qr[d + 1] + kk.z * qr[d + 2] + kk.w * qr[d + 3];
        }
        ob[(size_t)e * NPIX] = s * inv;
    }
}

// ---------------------------------------------------------------------------
extern "C" void kernel_launch(void* const* d_in, const int* in_sizes, int n_in,
                              void* d_out, int out_size)
{
    const float* x    = (const float*)d_in[0];
    const float* pos  = (const float*)d_in[1];
    const float* w_qk = (const float*)d_in[2];
    const float* w_v  = (const float*)d_in[3];
    const float* w_o  = (const float*)d_in[4];
    float* out = (float*)d_out;

    dim3 thr(256);

    // 1) qk = relu(w_qk @ (x+pos))   [B,1024,N]
    gemm_qk<<<dim3(NPIX / BNT, 1024 / BMT, BATCH), thr>>>(w_qk, x, pos);

    // 2) v = w_v @ x                 [B,512,N]
    gemm_v<<<dim3(NPIX / BNT, 512 / BMT, BATCH), thr>>>(w_v, x);

    // 3) kv = v_pad @ k^T            [B,H,65,64]
    kv_kernel<<<BATCH * NHEAD, 256>>>();

    // 4) out = normalize(kv @ q)     [B,512,N]  (in-place over g_V)
    attn_out_kernel<<<dim3(NPIX / 256, BATCH * NHEAD), 256>>>();

    // 5) final = w_o @ out           [B,512,N]
    gemm_o<<<dim3(NPIX / BNT, 512 / BMT, BATCH), thr>>>(w_o, out);
}

// round 4
// speedup vs baseline: 2.3210x; 1.1454x over previous
#include <cuda_runtime.h>
#include <cstdint>

// Problem constants
#define BATCH 16
#define CCH   512
#define NPIX  4096          // 64*64
#define NHEAD 8
#define HDIM  64
#define EPS   1e-6f

// Tensor-core GEMM tile config
#define BMT 128
#define BNT 128
#define BKT 32

// Scratch (device globals - no allocation at launch time).
__device__ float g_QK[(size_t)BATCH * 1024 * NPIX];   // relu(w_qk @ (x+pos)): q = ch 0..511, k = ch 512..1023
__device__ float g_V [(size_t)BATCH * CCH  * NPIX];   // V, then attention output (reused)
__device__ float g_KV[(size_t)BATCH * NHEAD * 65 * 64];

// ---------------------------------------------------------------------------
// tf32 helpers
// ---------------------------------------------------------------------------
__device__ __forceinline__ uint32_t f2tf32(float f) {
    uint32_t r;
    asm("cvt.rna.tf32.f32 %0, %1;" : "=r"(r) : "f"(f));
    return r;
}

__device__ __forceinline__ void mma_tf32(
    float& c0, float& c1, float& c2, float& c3,
    uint32_t a0, uint32_t a1, uint32_t a2, uint32_t a3,
    uint32_t b0, uint32_t b1)
{
    asm volatile(
        "mma.sync.aligned.m16n8k8.row.col.f32.tf32.tf32.f32 "
        "{%0,%1,%2,%3}, {%4,%5,%6,%7}, {%8,%9}, {%0,%1,%2,%3};"
        : "+f"(c0), "+f"(c1), "+f"(c2), "+f"(c3)
        : "r"(a0), "r"(a1), "r"(a2), "r"(a3), "r"(b0), "r"(b1));
}

// ---------------------------------------------------------------------------
// Tensor-core batched GEMM: C[b] (MxN) = A (MxK shared weights) * X[b] (KxN)
// Row-major. 256 threads, 128x128 tile, BK=32.
// 8 warps in 4x2 grid; each warp computes 32x64 via m16n8k8 tf32 mma.
// tf32 conversion happens ONCE at smem-store time; inner loop is pure LDS+MMA.
// Register-staged global loads overlap ldg with compute on previous tile.
// ---------------------------------------------------------------------------
#define AS_STRIDE 36    // pad: (group*36+tig)%32 = (group*4+tig)%32 -> conflict-free
#define XS_STRIDE 136   // pad: (tig*136+group)%32 = (tig*8+group)%32 -> conflict-free

template<bool FUSE_ADD, bool RELU>
__device__ __forceinline__ void gemm_tc_body(
    const float* __restrict__ A,
    const float* __restrict__ X0,
    const float* __restrict__ X1,
    float* __restrict__ C,
    int M, int K, int N)
{
    const int b = blockIdx.z;
    const float* X0b = X0 + (size_t)b * K * N;
    const float* X1b = FUSE_ADD ? (X1 + (size_t)b * K * N) : nullptr;
    float* Cb = C + (size_t)b * M * N;

    const int tileM = blockIdx.y * BMT;
    const int tileN = blockIdx.x * BNT;

    __shared__ uint32_t As[BMT][AS_STRIDE];   // [m][k]  (tf32 bits)
    __shared__ uint32_t Xs[BKT][XS_STRIDE];   // [k][n]  (tf32 bits)

    const int tid   = threadIdx.x;
    const int warp  = tid >> 5;
    const int lane  = tid & 31;
    const int group = lane >> 2;           // 0..7
    const int tig   = lane & 3;            // 0..3
    const int warp_m = warp >> 1;          // 0..3
    const int warp_n = warp & 1;           // 0..1
    const int m0 = warp_m * 32;
    const int n0 = warp_n * 64;

    float acc[2][8][4];
#pragma unroll
    for (int mt = 0; mt < 2; mt++)
#pragma unroll
        for (int nt = 0; nt < 8; nt++)
#pragma unroll
            for (int i = 0; i < 4; i++) acc[mt][nt][i] = 0.0f;

    // staging registers for the next tile
    float4 ar[4], xv[4];

    auto load_regs = [&](int k0) {
#pragma unroll
        for (int i = 0; i < 4; i++) {
            int f = tid + i * 256;         // 0..1023 (float4 index)
            int arow = f >> 3, ac4 = f & 7;
            ar[i] = *(const float4*)(A + (size_t)(tileM + arow) * K + k0 + ac4 * 4);
            int krow = f >> 5, n4 = f & 31;
            size_t off = (size_t)(k0 + krow) * N + tileN + n4 * 4;
            float4 v = *(const float4*)(X0b + off);
            if (FUSE_ADD) {
                float4 p = *(const float4*)(X1b + off);
                v.x += p.x; v.y += p.y; v.z += p.z; v.w += p.w;
            }
            xv[i] = v;
        }
    };

    // convert to tf32 and store into smem
    auto store_smem = [&]() {
#pragma unroll
        for (int i = 0; i < 4; i++) {
            int f = tid + i * 256;
            int arow = f >> 3, ac4 = f & 7;
            uint4 at;
            at.x = f2tf32(ar[i].x); at.y = f2tf32(ar[i].y);
            at.z = f2tf32(ar[i].z); at.w = f2tf32(ar[i].w);
            *(uint4*)(&As[arow][ac4 * 4]) = at;
            int krow = f >> 5, n4 = f & 31;
            uint4 xt;
            xt.x = f2tf32(xv[i].x); xt.y = f2tf32(xv[i].y);
            xt.z = f2tf32(xv[i].z); xt.w = f2tf32(xv[i].w);
            *(uint4*)(&Xs[krow][n4 * 4]) = xt;
        }
    };

    // compute on current smem tile: pure LDS + MMA
    auto compute = [&]() {
#pragma unroll
        for (int ks = 0; ks < BKT / 8; ks++) {
            const int k = ks * 8;
            uint32_t af[2][4];
#pragma unroll
            for (int mt = 0; mt < 2; mt++) {
                int r = m0 + mt * 16 + group;
                af[mt][0] = As[r    ][k + tig];
                af[mt][1] = As[r + 8][k + tig];
                af[mt][2] = As[r    ][k + tig + 4];
                af[mt][3] = As[r + 8][k + tig + 4];
            }
            uint32_t bf[8][2];
#pragma unroll
            for (int nt = 0; nt < 8; nt++) {
                int c = n0 + nt * 8 + group;
                bf[nt][0] = Xs[k + tig    ][c];
                bf[nt][1] = Xs[k + tig + 4][c];
            }
#pragma unroll
            for (int mt = 0; mt < 2; mt++)
#pragma unroll
                for (int nt = 0; nt < 8; nt++)
                    mma_tf32(acc[mt][nt][0], acc[mt][nt][1],
                             acc[mt][nt][2], acc[mt][nt][3],
                             af[mt][0], af[mt][1], af[mt][2], af[mt][3],
                             bf[nt][0], bf[nt][1]);
        }
    };

    load_regs(0);
    store_smem();
    __syncthreads();

#pragma unroll 1
    for (int k0 = BKT; k0 < K; k0 += BKT) {
        load_regs(k0);       // ldg overlaps with compute below
        compute();
        __syncthreads();
        store_smem();
        __syncthreads();
    }
    compute();

    // ---- epilogue ----
#pragma unroll
    for (int mt = 0; mt < 2; mt++) {
        int r = tileM + m0 + mt * 16 + group;
#pragma unroll
        for (int nt = 0; nt < 8; nt++) {
            int c = tileN + n0 + nt * 8 + tig * 2;
            float2 v0, v1;
            v0.x = acc[mt][nt][0]; v0.y = acc[mt][nt][1];
            v1.x = acc[mt][nt][2]; v1.y = acc[mt][nt][3];
            if (RELU) {
                v0.x = fmaxf(v0.x, 0.0f); v0.y = fmaxf(v0.y, 0.0f);
                v1.x = fmaxf(v1.x, 0.0f); v1.y = fmaxf(v1.y, 0.0f);
            }
            *(float2*)(Cb + (size_t)r * N + c)       = v0;
            *(float2*)(Cb + (size_t)(r + 8) * N + c) = v1;
        }
    }
}

__global__ __launch_bounds__(256) void gemm_qk(
    const float* __restrict__ A, const float* __restrict__ x,
    const float* __restrict__ pos)
{
    gemm_tc_body<true, true>(A, x, pos, g_QK, 1024, CCH, NPIX);
}

__global__ __launch_bounds__(256) void gemm_v(
    const float* __restrict__ A, const float* __restrict__ x)
{
    gemm_tc_body<false, false>(A, x, nullptr, g_V, 512, CCH, NPIX);
}

__global__ __launch_bounds__(256) void gemm_o(
    const float* __restrict__ A, float* __restrict__ out)
{
    gemm_tc_body<false, false>(A, g_V, nullptr, out, 512, CCH, NPIX);
}

// ---------------------------------------------------------------------------
// KV kernel: per (b,h): kv[e][d] = sum_n v[e][n]*k[d][n] for e,d in [0,64),
// plus kv[64][d] = sum_n k[d][n] (the ones-row of v_pad).
// One block per (b,h) = 128 blocks, 256 threads, 4x4 per thread (16x16 grid).
// ---------------------------------------------------------------------------
__global__ __launch_bounds__(256) void kv_kernel()
{
    const int bh = blockIdx.x;
    const int b = bh >> 3, h = bh & 7;
    const float* kp = g_QK + ((size_t)b * 1024 + 512 + h * 64) * NPIX;
    const float* vp = g_V  + ((size_t)b * 512  +       h * 64) * NPIX;

    __shared__ float Vs[64][65];   // [nn][e]
    __shared__ float Ks[64][65];   // [nn][d]

    const int tid = threadIdx.x;
    const int tx = tid & 15;       // d group
    const int ty = tid >> 4;       // e group

    float acc[4][4];
#pragma unroll
    for (int i = 0; i < 4; i++)
#pragma unroll
        for (int j = 0; j < 4; j++) acc[i][j] = 0.0f;
    float ksum = 0.0f;

    for (int n0 = 0; n0 < NPIX; n0 += 64) {
#pragma unroll
        for (int i = 0; i < 16; i++) {
            int idx = tid + i * 256;          // 0..4095
            int e  = idx >> 6;
            int nn = idx & 63;
            Vs[nn][e] = vp[(size_t)e * NPIX + n0 + nn];
            Ks[nn][e] = kp[(size_t)e * NPIX + n0 + nn];
        }
        __syncthreads();

#pragma unroll 8
        for (int nn = 0; nn < 64; nn++) {
            float vv[4], kk[4];
#pragma unroll
            for (int i = 0; i < 4; i++) vv[i] = Vs[nn][ty * 4 + i];
#pragma unroll
            for (int j = 0; j < 4; j++) kk[j] = Ks[nn][tx * 4 + j];
#pragma unroll
            for (int i = 0; i < 4; i++)
#pragma unroll
                for (int j = 0; j < 4; j++)
                    acc[i][j] += vv[i] * kk[j];
        }
        if (tid < 64) {
#pragma unroll 8
            for (int nn = 0; nn < 64; nn++) ksum += Ks[nn][tid];
        }
        __syncthreads();
    }

    float* kvb = g_KV + (size_t)bh * 65 * 64;
#pragma unroll
    for (int i = 0; i < 4; i++)
#pragma unroll
        for (int j = 0; j < 4; j++)
            kvb[(ty * 4 + i) * 64 + tx * 4 + j] = acc[i][j];
    if (tid < 64) kvb[64 * 64 + tid] = ksum;
}

// ---------------------------------------------------------------------------
// Attention output: per (b,h), per pixel n:
//   norm = sum_d kv[64][d]*q[d][n];  out[e][n] = (sum_d kv[e][d]*q[d][n]) / (norm+eps)
// grid (NPIX/256, B*NH), 256 threads, one pixel per thread.
// Writes the result in-place into g_V (V data already consumed by kv_kernel).
// ---------------------------------------------------------------------------
__global__ __launch_bounds__(256) void attn_out_kernel()
{
    const int bh = blockIdx.y;
    const int b = bh >> 3, h = bh & 7;
    const int n = blockIdx.x * 256 + threadIdx.x;

    __shared__ float kvs[65][64];
    const float* kvb = g_KV + (size_t)bh * 65 * 64;
    for (int i = threadIdx.x; i < 65 * 64; i += 256)
        ((float*)kvs)[i] = kvb[i];
    __syncthreads();

    const float* q = g_QK + ((size_t)b * 1024 + h * 64) * NPIX;
    float qr[64];
#pragma unroll
    for (int d = 0; d < 64; d++) qr[d] = q[(size_t)d * NPIX + n];

    float norm = 0.0f;
#pragma unroll
    for (int d = 0; d < 64; d += 4) {
        float4 kk = *(float4*)(&kvs[64][d]);
        norm += kk.x * qr[d] + kk.y * qr[d + 1] + kk.z * qr[d + 2] + kk.w * qr[d + 3];
    }
    const float inv = 1.0f / (norm + EPS);

    float* ob = g_V + ((size_t)b * 512 + h * 64) * NPIX + n;
#pragma unroll 2
    for (int e = 0; e < 64; e++) {
        float s = 0.0f;
#pragma unroll
        for (int d = 0; d < 64; d += 4) {
            float4 kk = *(float4*)(&kvs[e][d]);
            s += kk.x * qr[d] + kk.y * qr[d + 1] + kk.z * qr[d + 2] + kk.w * qr[d + 3];
        }
        ob[(size_t)e * NPIX] = s * inv;
    }
}

// ---------------------------------------------------------------------------
extern "C" void kernel_launch(void* const* d_in, const int* in_sizes, int n_in,
                              void* d_out, int out_size)
{
    const float* x    = (const float*)d_in[0];
    const float* pos  = (const float*)d_in[1];
    const float* w_qk = (const float*)d_in[2];
    const float* w_v  = (const float*)d_in[3];
    const float* w_o  = (const float*)d_in[4];
    float* out = (float*)d_out;

    dim3 thr(256);

    // 1) qk = relu(w_qk @ (x+pos))   [B,1024,N]
    gemm_qk<<<dim3(NPIX / BNT, 1024 / BMT, BATCH), thr>>>(w_qk, x, pos);

    // 2) v = w_v @ x                 [B,512,N]
    gemm_v<<<dim3(NPIX / BNT, 512 / BMT, BATCH), thr>>>(w_v, x);

    // 3) kv = v_pad @ k^T            [B,H,65,64]
    kv_kernel<<<BATCH * NHEAD, 256>>>();

    // 4) out = normalize(kv @ q)     [B,512,N]  (in-place over g_V)
    attn_out_kernel<<<dim3(NPIX / 256, BATCH * NHEAD), 256>>>();

    // 5) final = w_o @ out           [B,512,N]
    gemm_o<<<dim3(NPIX / BNT, 512 / BMT, BATCH), thr>>>(w_o, out);
}

// round 5
// speedup vs baseline: 2.6349x; 1.1352x over previous
#include <cuda_runtime.h>
#include <cstdint>

// Problem constants
#define BATCH 16
#define CCH   512
#define NPIX  4096          // 64*64
#define NHEAD 8
#define HDIM  64
#define EPS   1e-6f

// Tensor-core GEMM tile config
#define BMT 128
#define BNT 128
#define BKT 32

// Scratch (device globals - no allocation at launch time).
__device__ float g_QK[(size_t)BATCH * 1024 * NPIX];   // relu(w_qk @ (x+pos)): q = ch 0..511, k = ch 512..1023
__device__ float g_V [(size_t)BATCH * CCH  * NPIX];   // V, then attention output (reused)
__device__ float g_KV[(size_t)BATCH * NHEAD * 65 * 64];

// ---------------------------------------------------------------------------
// tf32 helpers
// ---------------------------------------------------------------------------
__device__ __forceinline__ uint32_t f2tf32(float f) {
    uint32_t r;
    asm("cvt.rna.tf32.f32 %0, %1;" : "=r"(r) : "f"(f));
    return r;
}

__device__ __forceinline__ void mma_tf32(
    float& c0, float& c1, float& c2, float& c3,
    uint32_t a0, uint32_t a1, uint32_t a2, uint32_t a3,
    uint32_t b0, uint32_t b1)
{
    asm volatile(
        "mma.sync.aligned.m16n8k8.row.col.f32.tf32.tf32.f32 "
        "{%0,%1,%2,%3}, {%4,%5,%6,%7}, {%8,%9}, {%0,%1,%2,%3};"
        : "+f"(c0), "+f"(c1), "+f"(c2), "+f"(c3)
        : "r"(a0), "r"(a1), "r"(a2), "r"(a3), "r"(b0), "r"(b1));
}

// ---------------------------------------------------------------------------
// Tensor-core batched GEMM: C[b] (MxN) = A (MxK shared weights) * X[b] (KxN)
// (unchanged from R4)
// ---------------------------------------------------------------------------
#define AS_STRIDE 36
#define XS_STRIDE 136

template<bool FUSE_ADD, bool RELU>
__device__ __forceinline__ void gemm_tc_body(
    const float* __restrict__ A,
    const float* __restrict__ X0,
    const float* __restrict__ X1,
    float* __restrict__ C,
    int M, int K, int N)
{
    const int b = blockIdx.z;
    const float* X0b = X0 + (size_t)b * K * N;
    const float* X1b = FUSE_ADD ? (X1 + (size_t)b * K * N) : nullptr;
    float* Cb = C + (size_t)b * M * N;

    const int tileM = blockIdx.y * BMT;
    const int tileN = blockIdx.x * BNT;

    __shared__ uint32_t As[BMT][AS_STRIDE];
    __shared__ uint32_t Xs[BKT][XS_STRIDE];

    const int tid   = threadIdx.x;
    const int warp  = tid >> 5;
    const int lane  = tid & 31;
    const int group = lane >> 2;
    const int tig   = lane & 3;
    const int warp_m = warp >> 1;
    const int warp_n = warp & 1;
    const int m0 = warp_m * 32;
    const int n0 = warp_n * 64;

    float acc[2][8][4];
#pragma unroll
    for (int mt = 0; mt < 2; mt++)
#pragma unroll
        for (int nt = 0; nt < 8; nt++)
#pragma unroll
            for (int i = 0; i < 4; i++) acc[mt][nt][i] = 0.0f;

    float4 ar[4], xv[4];

    auto load_regs = [&](int k0) {
#pragma unroll
        for (int i = 0; i < 4; i++) {
            int f = tid + i * 256;
            int arow = f >> 3, ac4 = f & 7;
            ar[i] = *(const float4*)(A + (size_t)(tileM + arow) * K + k0 + ac4 * 4);
            int krow = f >> 5, n4 = f & 31;
            size_t off = (size_t)(k0 + krow) * N + tileN + n4 * 4;
            float4 v = *(const float4*)(X0b + off);
            if (FUSE_ADD) {
                float4 p = *(const float4*)(X1b + off);
                v.x += p.x; v.y += p.y; v.z += p.z; v.w += p.w;
            }
            xv[i] = v;
        }
    };

    auto store_smem = [&]() {
#pragma unroll
        for (int i = 0; i < 4; i++) {
            int f = tid + i * 256;
            int arow = f >> 3, ac4 = f & 7;
            uint4 at;
            at.x = f2tf32(ar[i].x); at.y = f2tf32(ar[i].y);
            at.z = f2tf32(ar[i].z); at.w = f2tf32(ar[i].w);
            *(uint4*)(&As[arow][ac4 * 4]) = at;
            int krow = f >> 5, n4 = f & 31;
            uint4 xt;
            xt.x = f2tf32(xv[i].x); xt.y = f2tf32(xv[i].y);
            xt.z = f2tf32(xv[i].z); xt.w = f2tf32(xv[i].w);
            *(uint4*)(&Xs[krow][n4 * 4]) = xt;
        }
    };

    auto compute = [&]() {
#pragma unroll
        for (int ks = 0; ks < BKT / 8; ks++) {
            const int k = ks * 8;
            uint32_t af[2][4];
#pragma unroll
            for (int mt = 0; mt < 2; mt++) {
                int r = m0 + mt * 16 + group;
                af[mt][0] = As[r    ][k + tig];
                af[mt][1] = As[r + 8][k + tig];
                af[mt][2] = As[r    ][k + tig + 4];
                af[mt][3] = As[r + 8][k + tig + 4];
            }
            uint32_t bf[8][2];
#pragma unroll
            for (int nt = 0; nt < 8; nt++) {
                int c = n0 + nt * 8 + group;
                bf[nt][0] = Xs[k + tig    ][c];
                bf[nt][1] = Xs[k + tig + 4][c];
            }
#pragma unroll
            for (int mt = 0; mt < 2; mt++)
#pragma unroll
                for (int nt = 0; nt < 8; nt++)
                    mma_tf32(acc[mt][nt][0], acc[mt][nt][1],
                             acc[mt][nt][2], acc[mt][nt][3],
                             af[mt][0], af[mt][1], af[mt][2], af[mt][3],
                             bf[nt][0], bf[nt][1]);
        }
    };

    load_regs(0);
    store_smem();
    __syncthreads();

#pragma unroll 1
    for (int k0 = BKT; k0 < K; k0 += BKT) {
        load_regs(k0);
        compute();
        __syncthreads();
        store_smem();
        __syncthreads();
    }
    compute();

#pragma unroll
    for (int mt = 0; mt < 2; mt++) {
        int r = tileM + m0 + mt * 16 + group;
#pragma unroll
        for (int nt = 0; nt < 8; nt++) {
            int c = tileN + n0 + nt * 8 + tig * 2;
            float2 v0, v1;
            v0.x = acc[mt][nt][0]; v0.y = acc[mt][nt][1];
            v1.x = acc[mt][nt][2]; v1.y = acc[mt][nt][3];
            if (RELU) {
                v0.x = fmaxf(v0.x, 0.0f); v0.y = fmaxf(v0.y, 0.0f);
                v1.x = fmaxf(v1.x, 0.0f); v1.y = fmaxf(v1.y, 0.0f);
            }
            *(float2*)(Cb + (size_t)r * N + c)       = v0;
            *(float2*)(Cb + (size_t)(r + 8) * N + c) = v1;
        }
    }
}

__global__ __launch_bounds__(256) void gemm_qk(
    const float* __restrict__ A, const float* __restrict__ x,
    const float* __restrict__ pos)
{
    gemm_tc_body<true, true>(A, x, pos, g_QK, 1024, CCH, NPIX);
}

__global__ __launch_bounds__(256) void gemm_v(
    const float* __restrict__ A, const float* __restrict__ x)
{
    gemm_tc_body<false, false>(A, x, nullptr, g_V, 512, CCH, NPIX);
}

__global__ __launch_bounds__(256) void gemm_o(
    const float* __restrict__ A, float* __restrict__ out)
{
    gemm_tc_body<false, false>(A, g_V, nullptr, out, 512, CCH, NPIX);
}

// ---------------------------------------------------------------------------
// KV kernel (tensor-core): per (b,h):
//   D[80,64] = Vpad[80,Npix] @ K^T, where Vpad rows 0..63 = V, row 64 = ones,
//   rows 65..79 = zeros. D rows 0..64 -> g_KV (row 64 is the normalizer row).
// 128 CTAs, 256 threads = 8 warps; warp w owns D cols [8w, 8w+8): 5 m16 x 1 n8.
// ---------------------------------------------------------------------------
#define KVS 68   // smem stride (64 + 4 pad)

__global__ __launch_bounds__(256) void kv_mma_kernel()
{
    const int bh = blockIdx.x;
    const int b = bh >> 3, h = bh & 7;
    const float* kp = g_QK + ((size_t)b * 1024 + 512 + h * 64) * NPIX;
    const float* vp = g_V  + ((size_t)b * 512  +       h * 64) * NPIX;

    __shared__ uint32_t Vs[80][KVS];   // tf32 bits; rows 64..79 constant pad
    __shared__ uint32_t Ks[64][KVS];

    const int tid  = threadIdx.x;
    const int warp = tid >> 5;
    const int lane = tid & 31;
    const int group = lane >> 2;
    const int tig   = lane & 3;

    // init pad rows once (row 64 = 1.0, rows 65..79 = 0)
    for (int i = tid; i < 16 * KVS; i += 256) {
        int r = 64 + i / KVS, c = i % KVS;
        Vs[r][c] = (r == 64) ? __float_as_uint(1.0f) : 0u;
    }

    float acc[5][4];
#pragma unroll
    for (int mt = 0; mt < 5; mt++)
#pragma unroll
        for (int i = 0; i < 4; i++) acc[mt][i] = 0.0f;

    for (int n0 = 0; n0 < NPIX; n0 += 64) {
        __syncthreads();   // prev compute done before overwrite (also covers pad init)
        // load 64x64 V and K tiles: 1024 float4 each -> 4 per thread each
#pragma unroll
        for (int i = 0; i < 4; i++) {
            int f = tid + i * 256;          // 0..1023
            int row = f >> 4, c4 = f & 15;
            float4 v = *(const float4*)(vp + (size_t)row * NPIX + n0 + c4 * 4);
            uint4 vt;
            vt.x = f2tf32(v.x); vt.y = f2tf32(v.y); vt.z = f2tf32(v.z); vt.w = f2tf32(v.w);
            *(uint4*)(&Vs[row][c4 * 4]) = vt;
            float4 kk = *(const float4*)(kp + (size_t)row * NPIX + n0 + c4 * 4);
            uint4 kt;
            kt.x = f2tf32(kk.x); kt.y = f2tf32(kk.y); kt.z = f2tf32(kk.z); kt.w = f2tf32(kk.w);
            *(uint4*)(&Ks[row][c4 * 4]) = kt;
        }
        __syncthreads();

#pragma unroll
        for (int ks = 0; ks < 8; ks++) {
            const int k = ks * 8;
            uint32_t b0 = Ks[warp * 8 + group][k + tig];
            uint32_t b1 = Ks[warp * 8 + group][k + tig + 4];
#pragma unroll
            for (int mt = 0; mt < 5; mt++) {
                int r = mt * 16 + group;
                uint32_t a0 = Vs[r    ][k + tig];
                uint32_t a1 = Vs[r + 8][k + tig];
                uint32_t a2 = Vs[r    ][k + tig + 4];
                uint32_t a3 = Vs[r + 8][k + tig + 4];
                mma_tf32(acc[mt][0], acc[mt][1], acc[mt][2], acc[mt][3],
                         a0, a1, a2, a3, b0, b1);
            }
        }
    }

    // epilogue: rows 0..64 valid
    float* kvb = g_KV + (size_t)bh * 65 * 64;
#pragma unroll
    for (int mt = 0; mt < 5; mt++) {
        int r0 = mt * 16 + group;
        int r1 = r0 + 8;
        int c = warp * 8 + tig * 2;
        if (r0 < 65) {
            kvb[r0 * 64 + c]     = acc[mt][0];
            kvb[r0 * 64 + c + 1] = acc[mt][1];
        }
        if (r1 < 65) {
            kvb[r1 * 64 + c]     = acc[mt][2];
            kvb[r1 * 64 + c + 1] = acc[mt][3];
        }
    }
}

// ---------------------------------------------------------------------------
// Attention output (tensor-core): per (b,h, 128-pixel tile):
//   D[80,128] = KVpad[80,64] @ Q[64,128]; rows 0..63 -> out, row 64 -> norm.
//   out[e,n] = D[e,n] / (D[64,n] + eps), written in-place into g_V.
// grid (NPIX/128, B*NH), 256 threads = 8 warps; warp w owns cols [16w,16w+16).
// ---------------------------------------------------------------------------
#define QS 136   // Q smem stride (128 + 8 pad)

__global__ __launch_bounds__(256) void attn_mma_kernel()
{
    const int bh = blockIdx.y;
    const int b = bh >> 3, h = bh & 7;
    const int ntile = blockIdx.x * 128;

    __shared__ uint32_t As[80][KVS];    // KVpad tf32
    __shared__ uint32_t Qs[64][QS];     // Q tile tf32, [d][n]
    __shared__ float norms[8][16];

    const int tid  = threadIdx.x;
    const int warp = tid >> 5;
    const int lane = tid & 31;
    const int group = lane >> 2;
    const int tig   = lane & 3;

    // load KVpad: rows 0..64 from g_KV, rows 65..79 zero
    const float* kvb = g_KV + (size_t)bh * 65 * 64;
    for (int i = tid; i < 80 * 64; i += 256) {
        int r = i >> 6, c = i & 63;
        As[r][c] = (r < 65) ? f2tf32(kvb[i]) : 0u;
    }
    // load Q tile [64][128]
    const float* q = g_QK + ((size_t)b * 1024 + h * 64) * NPIX + ntile;
#pragma unroll
    for (int i = 0; i < 8; i++) {
        int f = tid + i * 256;            // 0..2047 float4 idx
        int row = f >> 5, c4 = f & 31;
        float4 v = *(const float4*)(q + (size_t)row * NPIX + c4 * 4);
        uint4 t;
        t.x = f2tf32(v.x); t.y = f2tf32(v.y); t.z = f2tf32(v.z); t.w = f2tf32(v.w);
        *(uint4*)(&Qs[row][c4 * 4]) = t;
    }
    __syncthreads();

    float acc[5][2][4];
#pragma unroll
    for (int mt = 0; mt < 5; mt++)
#pragma unroll
        for (int nt = 0; nt < 2; nt++)
#pragma unroll
            for (int i = 0; i < 4; i++) acc[mt][nt][i] = 0.0f;

#pragma unroll
    for (int ks = 0; ks < 8; ks++) {
        const int k = ks * 8;
        uint32_t bf[2][2];
#pragma unroll
        for (int nt = 0; nt < 2; nt++) {
            int c = warp * 16 + nt * 8 + group;
            bf[nt][0] = Qs[k + tig    ][c];
            bf[nt][1] = Qs[k + tig + 4][c];
        }
#pragma unroll
        for (int mt = 0; mt < 5; mt++) {
            int r = mt * 16 + group;
            uint32_t a0 = As[r    ][k + tig];
            uint32_t a1 = As[r + 8][k + tig];
            uint32_t a2 = As[r    ][k + tig + 4];
            uint32_t a3 = As[r + 8][k + tig + 4];
#pragma unroll
            for (int nt = 0; nt < 2; nt++)
                mma_tf32(acc[mt][nt][0], acc[mt][nt][1],
                         acc[mt][nt][2], acc[mt][nt][3],
                         a0, a1, a2, a3, bf[nt][0], bf[nt][1]);
        }
    }

    // norm row = D[64][*]: held by mt=4, group==0 lanes (c0,c1)
    if (group == 0) {
#pragma unroll
        for (int nt = 0; nt < 2; nt++) {
            norms[warp][nt * 8 + tig * 2]     = acc[4][nt][0];
            norms[warp][nt * 8 + tig * 2 + 1] = acc[4][nt][1];
        }
    }
    __syncwarp();

    // divide and store rows 0..63 (mt 0..3)
    float* ob = g_V + ((size_t)b * 512 + h * 64) * NPIX + ntile;
#pragma unroll
    for (int nt = 0; nt < 2; nt++) {
        int cl = nt * 8 + tig * 2;
        float inv0 = 1.0f / (norms[warp][cl]     + EPS);
        float inv1 = 1.0f / (norms[warp][cl + 1] + EPS);
        int c = warp * 16 + cl;
#pragma unroll
        for (int mt = 0; mt < 4; mt++) {
            int r0 = mt * 16 + group;
            float2 v0, v1;
            v0.x = acc[mt][nt][0] * inv0; v0.y = acc[mt][nt][1] * inv1;
            v1.x = acc[mt][nt][2] * inv0; v1.y = acc[mt][nt][3] * inv1;
            *(float2*)(ob + (size_t)r0 * NPIX + c)       = v0;
            *(float2*)(ob + (size_t)(r0 + 8) * NPIX + c) = v1;
        }
    }
}

// ---------------------------------------------------------------------------
extern "C" void kernel_launch(void* const* d_in, const int* in_sizes, int n_in,
                              void* d_out, int out_size)
{
    const float* x    = (const float*)d_in[0];
    const float* pos  = (const float*)d_in[1];
    const float* w_qk = (const float*)d_in[2];
    const float* w_v  = (const float*)d_in[3];
    const float* w_o  = (const float*)d_in[4];
    float* out = (float*)d_out;

    dim3 thr(256);

    // 1) qk = relu(w_qk @ (x+pos))   [B,1024,N]
    gemm_qk<<<dim3(NPIX / BNT, 1024 / BMT, BATCH), thr>>>(w_qk, x, pos);

    // 2) v = w_v @ x                 [B,512,N]
    gemm_v<<<dim3(NPIX / BNT, 512 / BMT, BATCH), thr>>>(w_v, x);

    // 3) kv = v_pad @ k^T            [B,H,65,64]  (tensor cores)
    kv_mma_kernel<<<BATCH * NHEAD, 256>>>();

    // 4) out = normalize(kv @ q)     [B,512,N]  in-place over g_V (tensor cores)
    attn_mma_kernel<<<dim3(NPIX / 128, BATCH * NHEAD), 256>>>();

    // 5) final = w_o @ out           [B,512,N]
    gemm_o<<<dim3(NPIX / BNT, 512 / BMT, BATCH), thr>>>(w_o, out);
}